// round 3
// baseline (speedup 1.0000x reference)
#include <cuda_runtime.h>
#include <cstdint>
#include <math.h>

#define U_N 10000
#define G_N 3000
#define I_N 8000
#define DD 32
#define UI_N (U_N + I_N)   /* 18000 */
#define GI_N (G_N + I_N)   /* 11000 */
#define NNZ_UI 720000
#define NNZ_GI 440000
#define LM 20
#define B_N 4096
#define KSPLIT 8
#define FULL 0xffffffffu

// ----------------------------- static scratch -----------------------------
__device__ float g_bufA[UI_N * DD];
__device__ float g_bufB[UI_N * DD];
__device__ float g_bufC[UI_N * DD];
__device__ float g_sumUI[UI_N * DD];
__device__ float g_meanUI[UI_N * DD];
__device__ float g_giA[GI_N * DD];
__device__ float g_giB[GI_N * DD];
__device__ float g_sumGI[GI_N * DD];
__device__ float g_gpart[G_N * DD];
__device__ float g_gul[G_N * DD];
__device__ float g_gfinal[G_N * DD];
__device__ float g_iemb[I_N * DD];
__device__ float g_t1[U_N * DD];
__device__ float g_t2[U_N * DD];
__device__ float g_accU[U_N * DD];
__device__ float g_it1[I_N * DD];
__device__ float g_it2[I_N * DD];
__device__ float g_accI[I_N * DD];
__device__ float g_uiev[NNZ_UI];
__device__ float g_giev[NNZ_GI];
__device__ float g_part[KSPLIT * U_N * DD];

__device__ int g_uicnt[UI_N];
__device__ int g_uirp[UI_N + 1];
__device__ int g_uicur[UI_N];
__device__ int g_uiecol[NNZ_UI];
__device__ int g_gicnt[GI_N];
__device__ int g_girp[GI_N + 1];
__device__ int g_gicur[GI_N];
__device__ int g_giecol[NNZ_GI];

// ----------------------------- CSR build ----------------------------------
__global__ void k_zero_i(int* p, int n) {
    int i = blockIdx.x * blockDim.x + threadIdx.x;
    if (i < n) p[i] = 0;
}

__global__ void k_hist(const int* __restrict__ rows, int* cnt, int nnz) {
    int i = blockIdx.x * blockDim.x + threadIdx.x;
    if (i < nnz) atomicAdd(&cnt[rows[i]], 1);
}

// single block, 1024 threads: exclusive scan -> rowptr + cursor
__global__ void k_scan(const int* __restrict__ cnt, int* rp, int* cur, int n) {
    __shared__ int part[1024];
    int tid = threadIdx.x;
    int chunk = (n + 1023) >> 10;
    int s0 = tid * chunk;
    int s1 = min(s0 + chunk, n);
    int s = 0;
    for (int i = s0; i < s1; i++) s += cnt[i];
    part[tid] = s;
    __syncthreads();
    for (int off = 1; off < 1024; off <<= 1) {
        int v = (tid >= off) ? part[tid - off] : 0;
        __syncthreads();
        part[tid] += v;
        __syncthreads();
    }
    int base = (tid == 0) ? 0 : part[tid - 1];
    for (int i = s0; i < s1; i++) {
        rp[i] = base;
        cur[i] = base;
        base += cnt[i];
    }
    if (tid == 1023) rp[n] = part[1023];
}

__global__ void k_scatter(const int* __restrict__ rows, const int* __restrict__ cols,
                          const float* __restrict__ vals, int* cur,
                          int* ecol, float* eval, int nnz) {
    int i = blockIdx.x * blockDim.x + threadIdx.x;
    if (i >= nnz) return;
    int p = atomicAdd(&cur[rows[i]], 1);
    ecol[p] = cols[i];
    eval[p] = vals[i];
}

// ----------------------------- SpMM ---------------------------------------
// warp per row, lane = embedding column; atomic-free row gather
__global__ void k_spmm(const int* __restrict__ rp, const int* __restrict__ ecol,
                       const float* __restrict__ eval, const float* __restrict__ x,
                       float* __restrict__ out, float* __restrict__ accum, int nrows) {
    int r = blockIdx.x * 8 + (threadIdx.x >> 5);
    if (r >= nrows) return;
    int lane = threadIdx.x & 31;
    int s = __ldg(&rp[r]);
    int e = __ldg(&rp[r + 1]);
    float acc = 0.f;
    int i = s;
    for (; i + 4 <= e; i += 4) {
        int c0 = __ldg(&ecol[i]);
        int c1 = __ldg(&ecol[i + 1]);
        int c2 = __ldg(&ecol[i + 2]);
        int c3 = __ldg(&ecol[i + 3]);
        float v0 = __ldg(&eval[i]);
        float v1 = __ldg(&eval[i + 1]);
        float v2 = __ldg(&eval[i + 2]);
        float v3 = __ldg(&eval[i + 3]);
        acc = fmaf(v0, __ldg(&x[c0 * DD + lane]), acc);
        acc = fmaf(v1, __ldg(&x[c1 * DD + lane]), acc);
        acc = fmaf(v2, __ldg(&x[c2 * DD + lane]), acc);
        acc = fmaf(v3, __ldg(&x[c3 * DD + lane]), acc);
    }
    for (; i < e; i++)
        acc = fmaf(__ldg(&eval[i]), __ldg(&x[__ldg(&ecol[i]) * DD + lane]), acc);
    int idx = r * DD + lane;
    out[idx] = acc;
    accum[idx] += acc;
}

// SpMM over rows [0,nrows) with virtually-concatenated x = [xTop; xBot]
__global__ void k_spmm_dual(const int* __restrict__ rp, const int* __restrict__ ecol,
                            const float* __restrict__ eval,
                            const float* __restrict__ xTop, const float* __restrict__ xBot,
                            int split, float* __restrict__ accum, int nrows) {
    int r = blockIdx.x * 8 + (threadIdx.x >> 5);
    if (r >= nrows) return;
    int lane = threadIdx.x & 31;
    int s = __ldg(&rp[r]);
    int e = __ldg(&rp[r + 1]);
    float acc = 0.f;
    for (int i = s; i < e; i++) {
        int c = __ldg(&ecol[i]);
        float v = __ldg(&eval[i]);
        float xv = (c < split) ? __ldg(&xTop[c * DD + lane])
                               : __ldg(&xBot[(c - split) * DD + lane]);
        acc = fmaf(v, xv, acc);
    }
    accum[r * DD + lane] += acc;
}

// ----------------------------- dense GEMM ----------------------------------
// y[N,32] = A[N,N] @ x[N,32], split-K into KSPLIT partials (deterministic).
// CTA: 64 rows x 32 cols; thread (tx,ty): cols {2tx,2tx+1}, rows {4ty..4ty+3}.
// Inner uses packed fma.rn.f32x2 (FFMA2) for 2x fp32 throughput.
__global__ void __launch_bounds__(256) k_gemm(const float* __restrict__ A,
                                              const float* __restrict__ x,
                                              float* __restrict__ part, int N, int KS) {
    __shared__ __align__(16) float As[64 * 36];
    __shared__ __align__(16) float xs[32 * 34];
    int tid = threadIdx.x;
    int tx = tid & 15;
    int ty = tid >> 4;
    int row0 = blockIdx.x * 64;
    int kseg = blockIdx.y;
    int kbeg = kseg * KS;
    int kend = min(kbeg + KS, N);

    unsigned long long acc2[4] = {0ull, 0ull, 0ull, 0ull};

    for (int k0 = kbeg; k0 < kend; k0 += 32) {
#pragma unroll
        for (int l = 0; l < 8; l++) {
            int idx = tid + l * 256;
            int r = idx >> 5, kk = idx & 31;
            int gr = row0 + r, gk = k0 + kk;
            float v = 0.f;
            if (gr < N && gk < kend) v = A[(size_t)gr * N + gk];
            As[r * 36 + kk] = v;
        }
#pragma unroll
        for (int l = 0; l < 4; l++) {
            int idx = tid + l * 256;
            int kk = idx >> 5, c = idx & 31;
            int gk = k0 + kk;
            xs[kk * 34 + c] = (gk < kend) ? x[gk * 32 + c] : 0.f;
        }
        __syncthreads();
#pragma unroll
        for (int kq = 0; kq < 8; kq++) {
            unsigned long long xv0 = *reinterpret_cast<const unsigned long long*>(&xs[(kq * 4 + 0) * 34 + 2 * tx]);
            unsigned long long xv1 = *reinterpret_cast<const unsigned long long*>(&xs[(kq * 4 + 1) * 34 + 2 * tx]);
            unsigned long long xv2 = *reinterpret_cast<const unsigned long long*>(&xs[(kq * 4 + 2) * 34 + 2 * tx]);
            unsigned long long xv3 = *reinterpret_cast<const unsigned long long*>(&xs[(kq * 4 + 3) * 34 + 2 * tx]);
#pragma unroll
            for (int r = 0; r < 4; r++) {
                float4 a4 = *reinterpret_cast<const float4*>(&As[(ty * 4 + r) * 36 + kq * 4]);
                unsigned long long p;
                asm("mov.b64 %0, {%1, %1};" : "=l"(p) : "f"(a4.x));
                asm("fma.rn.f32x2 %0, %1, %2, %0;" : "+l"(acc2[r]) : "l"(p), "l"(xv0));
                asm("mov.b64 %0, {%1, %1};" : "=l"(p) : "f"(a4.y));
                asm("fma.rn.f32x2 %0, %1, %2, %0;" : "+l"(acc2[r]) : "l"(p), "l"(xv1));
                asm("mov.b64 %0, {%1, %1};" : "=l"(p) : "f"(a4.z));
                asm("fma.rn.f32x2 %0, %1, %2, %0;" : "+l"(acc2[r]) : "l"(p), "l"(xv2));
                asm("mov.b64 %0, {%1, %1};" : "=l"(p) : "f"(a4.w));
                asm("fma.rn.f32x2 %0, %1, %2, %0;" : "+l"(acc2[r]) : "l"(p), "l"(xv3));
            }
        }
        __syncthreads();
    }
#pragma unroll
    for (int r = 0; r < 4; r++) {
        int row = row0 + ty * 4 + r;
        if (row < N) {
            float lo, hi;
            asm("mov.b64 {%0, %1}, %2;" : "=f"(lo), "=f"(hi) : "l"(acc2[r]));
            float2 v = make_float2(lo, hi);
            *reinterpret_cast<float2*>(&part[((size_t)kseg * N + row) * 32 + 2 * tx]) = v;
        }
    }
}

// sum the KSPLIT partials; write y; update acc (init from xinit or accumulate)
__global__ void k_reduce(const float* __restrict__ part, float* __restrict__ y,
                         float* __restrict__ acc, const float* __restrict__ xinit,
                         int N, int initFlag) {
    int idx = blockIdx.x * blockDim.x + threadIdx.x;
    if (idx >= N * 32) return;
    float s = 0.f;
#pragma unroll
    for (int q = 0; q < KSPLIT; q++) s += part[(size_t)q * N * 32 + idx];
    y[idx] = s;
    if (initFlag) acc[idx] = xinit[idx] + s;
    else acc[idx] += s;
}

// ----------------------------- elementwise ---------------------------------
__global__ void k_initUI(const float* __restrict__ ue, const float* __restrict__ ie,
                         float* bufA, float* sum) {
    int i = blockIdx.x * blockDim.x + threadIdx.x;
    if (i >= UI_N * DD) return;
    float v = (i < U_N * DD) ? ue[i] : ie[i - U_N * DD];
    bufA[i] = v;
    sum[i] = v;
}

__global__ void k_initGI(const float* __restrict__ ge, const float* __restrict__ itemsrc,
                         float* giA, float* sum) {
    int i = blockIdx.x * blockDim.x + threadIdx.x;
    if (i >= GI_N * DD) return;
    float v = (i < G_N * DD) ? ge[i] : itemsrc[i - G_N * DD];
    giA[i] = v;
    sum[i] = v;
}

__global__ void k_scale(float* __restrict__ o, const float* __restrict__ in, float s, int n) {
    int i = blockIdx.x * blockDim.x + threadIdx.x;
    if (i < n) o[i] = in[i] * s;
}

__global__ void k_copy(float* __restrict__ o, const float* __restrict__ in, int n) {
    int i = blockIdx.x * blockDim.x + threadIdx.x;
    if (i < n) o[i] = in[i];
}

__global__ void k_add(float* __restrict__ o, const float* __restrict__ in, int n) {
    int i = blockIdx.x * blockDim.x + threadIdx.x;
    if (i < n) o[i] += in[i];
}

// ----------------------------- pooling / gate / predict --------------------
__global__ void k_pool(const int* __restrict__ users, const float* __restrict__ mask,
                       const float* __restrict__ accU, float* __restrict__ gul) {
    int g = blockIdx.x * 8 + (threadIdx.x >> 5);
    if (g >= G_N) return;
    int lane = threadIdx.x & 31;
    float a = 0.f;
#pragma unroll
    for (int l = 0; l < LM; l++) {
        int u = __ldg(&users[g * LM + l]);
        float m = __ldg(&mask[g * LM + l]);
        a = fmaf(m, __ldg(&accU[u * DD + lane]), a);
    }
    gul[g * DD + lane] = a;
}

__global__ void k_gate(const float* __restrict__ gpart, const float* __restrict__ gul,
                       const float* __restrict__ w1, const float* __restrict__ b1,
                       const float* __restrict__ w2, const float* __restrict__ b2,
                       float* __restrict__ gfinal) {
    int g = blockIdx.x * 8 + (threadIdx.x >> 5);
    if (g >= G_N) return;
    int lane = threadIdx.x & 31;
    float xg = gpart[g * DD + lane] * 0.25f;   // g_emb = gpart/4
    float xu = gul[g * DD + lane];
    float h1 = __ldg(&b1[lane]);
    float h2 = h1;
#pragma unroll
    for (int k = 0; k < 32; k++) {
        float w = __ldg(&w1[k * 32 + lane]);
        h1 = fmaf(__shfl_sync(FULL, xg, k), w, h1);
        h2 = fmaf(__shfl_sync(FULL, xu, k), w, h2);
    }
    h1 = fmaxf(h1, 0.f);
    h2 = fmaxf(h2, 0.f);
    float w2l = __ldg(&w2[lane]);
    float s1 = h1 * w2l;
    float s2 = h2 * w2l;
#pragma unroll
    for (int o = 16; o; o >>= 1) {
        s1 += __shfl_xor_sync(FULL, s1, o);
        s2 += __shfl_xor_sync(FULL, s2, o);
    }
    float bb = __ldg(&b2[0]);
    float wg = 1.f / (1.f + expf(-(s1 + bb)));
    float wu = 1.f / (1.f + expf(-(s2 + bb)));
    gfinal[g * DD + lane] = wg * xg + wu * xu;
}

__global__ void k_pred(const int* __restrict__ ginp, const int* __restrict__ iinp,
                       const float* __restrict__ gfinal, const float* __restrict__ accI,
                       const float* __restrict__ pw1, const float* __restrict__ pb1,
                       const float* __restrict__ pw2, const float* __restrict__ pb2,
                       float* __restrict__ out) {
    int b = blockIdx.x * 8 + (threadIdx.x >> 5);
    if (b >= B_N) return;
    int lane = threadIdx.x & 31;
    int g = __ldg(&ginp[b]);
    int it = __ldg(&iinp[b]);
    float t = gfinal[g * DD + lane] * accI[it * DD + lane];
    int j = lane & 7;
    float p = __ldg(&pb1[j]);
#pragma unroll
    for (int k = 0; k < 32; k++) {
        float a = __shfl_sync(FULL, t, k);
        p = fmaf(a, __ldg(&pw1[k * 8 + j]), p);
    }
    p = fmaxf(p, 0.f);
    float s = (lane < 8) ? p * __ldg(&pw2[j]) : 0.f;
#pragma unroll
    for (int o = 16; o; o >>= 1) s += __shfl_xor_sync(FULL, s, o);
    if (lane == 0) out[b] = 1.f / (1.f + expf(-(s + __ldg(&pb2[0]))));
}

// ----------------------------- launch --------------------------------------
extern "C" void kernel_launch(void* const* d_in, const int* in_sizes, int n_in,
                              void* d_out, int out_size) {
    (void)in_sizes; (void)n_in; (void)out_size;
    const int* ginp = (const int*)d_in[0];
    const int* iinp = (const int*)d_in[1];
    const float* user_emb = (const float*)d_in[2];
    const float* group_emb = (const float*)d_in[3];
    const float* item_emb = (const float*)d_in[4];
    const int* ui_rows = (const int*)d_in[5];
    const int* ui_cols = (const int*)d_in[6];
    const float* ui_vals = (const float*)d_in[7];
    const int* gi_rows = (const int*)d_in[8];
    const int* gi_cols = (const int*)d_in[9];
    const float* gi_vals = (const float*)d_in[10];
    const float* ovU = (const float*)d_in[11];
    const float* ovI = (const float*)d_in[12];
    const int* agu = (const int*)d_in[13];
    const float* agm = (const float*)d_in[14];
    const float* gw1 = (const float*)d_in[15];
    const float* gb1 = (const float*)d_in[16];
    const float* gw2 = (const float*)d_in[17];
    const float* gb2 = (const float*)d_in[18];
    const float* pw1 = (const float*)d_in[19];
    const float* pb1 = (const float*)d_in[20];
    const float* pw2 = (const float*)d_in[21];
    const float* pb2 = (const float*)d_in[22];
    float* out = (float*)d_out;

    float *bufA, *bufB, *bufC, *sumUI, *meanUI, *giA, *giB, *sumGI;
    float *gpart, *gul, *gfinal, *iemb, *t1, *t2, *accU, *it1, *it2, *accI;
    float *uiev, *giev, *part;
    int *uicnt, *uirp, *uicur, *uiecol, *gicnt, *girp, *gicur, *giecol;
    cudaGetSymbolAddress((void**)&bufA, g_bufA);
    cudaGetSymbolAddress((void**)&bufB, g_bufB);
    cudaGetSymbolAddress((void**)&bufC, g_bufC);
    cudaGetSymbolAddress((void**)&sumUI, g_sumUI);
    cudaGetSymbolAddress((void**)&meanUI, g_meanUI);
    cudaGetSymbolAddress((void**)&giA, g_giA);
    cudaGetSymbolAddress((void**)&giB, g_giB);
    cudaGetSymbolAddress((void**)&sumGI, g_sumGI);
    cudaGetSymbolAddress((void**)&gpart, g_gpart);
    cudaGetSymbolAddress((void**)&gul, g_gul);
    cudaGetSymbolAddress((void**)&gfinal, g_gfinal);
    cudaGetSymbolAddress((void**)&iemb, g_iemb);
    cudaGetSymbolAddress((void**)&t1, g_t1);
    cudaGetSymbolAddress((void**)&t2, g_t2);
    cudaGetSymbolAddress((void**)&accU, g_accU);
    cudaGetSymbolAddress((void**)&it1, g_it1);
    cudaGetSymbolAddress((void**)&it2, g_it2);
    cudaGetSymbolAddress((void**)&accI, g_accI);
    cudaGetSymbolAddress((void**)&uiev, g_uiev);
    cudaGetSymbolAddress((void**)&giev, g_giev);
    cudaGetSymbolAddress((void**)&part, g_part);
    cudaGetSymbolAddress((void**)&uicnt, g_uicnt);
    cudaGetSymbolAddress((void**)&uirp, g_uirp);
    cudaGetSymbolAddress((void**)&uicur, g_uicur);
    cudaGetSymbolAddress((void**)&uiecol, g_uiecol);
    cudaGetSymbolAddress((void**)&gicnt, g_gicnt);
    cudaGetSymbolAddress((void**)&girp, g_girp);
    cudaGetSymbolAddress((void**)&gicur, g_gicur);
    cudaGetSymbolAddress((void**)&giecol, g_giecol);

    // ---- CSR build for both graphs ----
    k_zero_i<<<(UI_N + 255) / 256, 256>>>(uicnt, UI_N);
    k_zero_i<<<(GI_N + 255) / 256, 256>>>(gicnt, GI_N);
    k_hist<<<(NNZ_UI + 255) / 256, 256>>>(ui_rows, uicnt, NNZ_UI);
    k_hist<<<(NNZ_GI + 255) / 256, 256>>>(gi_rows, gicnt, NNZ_GI);
    k_scan<<<1, 1024>>>(uicnt, uirp, uicur, UI_N);
    k_scan<<<1, 1024>>>(gicnt, girp, gicur, GI_N);
    k_scatter<<<(NNZ_UI + 255) / 256, 256>>>(ui_rows, ui_cols, ui_vals, uicur, uiecol, uiev, NNZ_UI);
    k_scatter<<<(NNZ_GI + 255) / 256, 256>>>(gi_rows, gi_cols, gi_vals, gicur, giecol, giev, NNZ_GI);

    // ---- user-item propagation (3 layers) ----
    k_initUI<<<(UI_N * DD + 255) / 256, 256>>>(user_emb, item_emb, bufA, sumUI);
    k_spmm<<<(UI_N + 7) / 8, 256>>>(uirp, uiecol, uiev, bufA, bufB, sumUI, UI_N);  // ui1
    k_spmm<<<(UI_N + 7) / 8, 256>>>(uirp, uiecol, uiev, bufB, bufC, sumUI, UI_N);  // ui2 (kept in bufC)
    k_spmm<<<(UI_N + 7) / 8, 256>>>(uirp, uiecol, uiev, bufC, bufA, sumUI, UI_N);  // ui3
    k_scale<<<(UI_N * DD + 255) / 256, 256>>>(meanUI, sumUI, 0.25f, UI_N * DD);

    // ---- group-item propagation ----
    k_initGI<<<(GI_N * DD + 255) / 256, 256>>>(group_emb, meanUI + U_N * DD, giA, sumGI);
    k_copy<<<(G_N * DD + 255) / 256, 256>>>(gpart, group_emb, G_N * DD);            // g_layers[0]
    k_spmm<<<(GI_N + 7) / 8, 256>>>(girp, giecol, giev, giA, giB, sumGI, GI_N);     // gi1
    k_spmm<<<(GI_N + 7) / 8, 256>>>(girp, giecol, giev, giB, giA, sumGI, GI_N);     // gi2 -> giA
    k_add<<<(G_N * DD + 255) / 256, 256>>>(gpart, giA, G_N * DD);                   // g_layers[2]
    k_spmm<<<(GI_N + 7) / 8, 256>>>(girp, giecol, giev, giA, giB, sumGI, GI_N);     // gi3
    k_scale<<<(I_N * DD + 255) / 256, 256>>>(iemb, sumGI + G_N * DD, 0.25f, I_N * DD);  // i_emb
    // g_layers[1]: spmm(concat(group_emb, item_emb))[:G]
    k_spmm_dual<<<(G_N + 7) / 8, 256>>>(girp, giecol, giev, group_emb, item_emb, G_N, gpart, G_N);
    // g_layers[3]: spmm(concat(group_emb, ui2_items))[:G]
    k_spmm_dual<<<(G_N + 7) / 8, 256>>>(girp, giecol, giev, group_emb, bufC + U_N * DD, G_N, gpart, G_N);

    // ---- user social power-series (2 dense GEMM layers) ----
    {
        int KS = (U_N + KSPLIT - 1) / KSPLIT;
        dim3 grid((U_N + 63) / 64, KSPLIT);
        k_gemm<<<grid, 256>>>(ovU, meanUI, part, U_N, KS);
        k_reduce<<<(U_N * DD + 255) / 256, 256>>>(part, t1, accU, meanUI, U_N, 1);
        k_gemm<<<grid, 256>>>(ovU, t1, part, U_N, KS);
        k_reduce<<<(U_N * DD + 255) / 256, 256>>>(part, t2, accU, meanUI, U_N, 0);
    }
    k_pool<<<(G_N + 7) / 8, 256>>>(agu, agm, accU, gul);
    k_gate<<<(G_N + 7) / 8, 256>>>(gpart, gul, gw1, gb1, gw2, gb2, gfinal);

    // ---- item social power-series ----
    {
        int KS = (I_N + KSPLIT - 1) / KSPLIT;
        dim3 grid((I_N + 63) / 64, KSPLIT);
        k_gemm<<<grid, 256>>>(ovI, iemb, part, I_N, KS);
        k_reduce<<<(I_N * DD + 255) / 256, 256>>>(part, it1, accI, iemb, I_N, 1);
        k_gemm<<<grid, 256>>>(ovI, it1, part, I_N, KS);
        k_reduce<<<(I_N * DD + 255) / 256, 256>>>(part, it2, accI, iemb, I_N, 0);
    }

    // ---- predict ----
    k_pred<<<(B_N + 7) / 8, 256>>>(ginp, iinp, gfinal, accI, pw1, pb1, pw2, pb2, out);
}

// round 5
// speedup vs baseline: 1.0481x; 1.0481x over previous
#include <cuda_runtime.h>
#include <cstdint>
#include <math.h>

#define U_N 10000
#define G_N 3000
#define I_N 8000
#define DD 32
#define UI_N (U_N + I_N)   /* 18000 */
#define GI_N (G_N + I_N)   /* 11000 */
#define NNZ_UI 720000
#define NNZ_GI 440000
#define LM 20
#define B_N 4096
#define KSPLIT 16
#define FULL 0xffffffffu

// ----------------------------- static scratch -----------------------------
__device__ float g_bufA[UI_N * DD];
__device__ float g_bufB[UI_N * DD];
__device__ float g_bufC[UI_N * DD];
__device__ float g_sumUI[UI_N * DD];
__device__ float g_meanUI[UI_N * DD];
__device__ float g_giA[GI_N * DD];
__device__ float g_giB[GI_N * DD];
__device__ float g_sumGI[GI_N * DD];
__device__ float g_gpart[G_N * DD];
__device__ float g_gul[G_N * DD];
__device__ float g_gfinal[G_N * DD];
__device__ float g_iemb[I_N * DD];
__device__ float g_t1[U_N * DD];
__device__ float g_t2[U_N * DD];
__device__ float g_accU[U_N * DD];
__device__ float g_it1[I_N * DD];
__device__ float g_it2[I_N * DD];
__device__ float g_accI[I_N * DD];
__device__ float g_uiev[NNZ_UI];
__device__ float g_giev[NNZ_GI];
__device__ float g_part[KSPLIT * U_N * DD];

__device__ int g_uicnt[UI_N];
__device__ int g_uirp[UI_N + 1];
__device__ int g_uicur[UI_N];
__device__ int g_uiecol[NNZ_UI];
__device__ int g_gicnt[GI_N];
__device__ int g_girp[GI_N + 1];
__device__ int g_gicur[GI_N];
__device__ int g_giecol[NNZ_GI];

// ----------------------------- CSR build ----------------------------------
__global__ void k_zero_i(int* p, int n) {
    int i = blockIdx.x * blockDim.x + threadIdx.x;
    if (i < n) p[i] = 0;
}

__global__ void k_hist(const int* __restrict__ rows, int* cnt, int nnz) {
    int i = blockIdx.x * blockDim.x + threadIdx.x;
    if (i < nnz) atomicAdd(&cnt[rows[i]], 1);
}

// single block, 1024 threads: exclusive scan -> rowptr + cursor
__global__ void k_scan(const int* __restrict__ cnt, int* rp, int* cur, int n) {
    __shared__ int part[1024];
    int tid = threadIdx.x;
    int chunk = (n + 1023) >> 10;
    int s0 = tid * chunk;
    int s1 = min(s0 + chunk, n);
    int s = 0;
    for (int i = s0; i < s1; i++) s += cnt[i];
    part[tid] = s;
    __syncthreads();
    for (int off = 1; off < 1024; off <<= 1) {
        int v = (tid >= off) ? part[tid - off] : 0;
        __syncthreads();
        part[tid] += v;
        __syncthreads();
    }
    int base = (tid == 0) ? 0 : part[tid - 1];
    for (int i = s0; i < s1; i++) {
        rp[i] = base;
        cur[i] = base;
        base += cnt[i];
    }
    if (tid == 1023) rp[n] = part[1023];
}

__global__ void k_scatter(const int* __restrict__ rows, const int* __restrict__ cols,
                          const float* __restrict__ vals, int* cur,
                          int* ecol, float* eval, int nnz) {
    int i = blockIdx.x * blockDim.x + threadIdx.x;
    if (i >= nnz) return;
    int p = atomicAdd(&cur[rows[i]], 1);
    ecol[p] = cols[i];
    eval[p] = vals[i];
}

// ----------------------------- SpMM ---------------------------------------
__global__ void k_spmm(const int* __restrict__ rp, const int* __restrict__ ecol,
                       const float* __restrict__ eval, const float* __restrict__ x,
                       float* __restrict__ out, float* __restrict__ accum, int nrows) {
    int r = blockIdx.x * 8 + (threadIdx.x >> 5);
    if (r >= nrows) return;
    int lane = threadIdx.x & 31;
    int s = __ldg(&rp[r]);
    int e = __ldg(&rp[r + 1]);
    float acc = 0.f;
    int i = s;
    for (; i + 4 <= e; i += 4) {
        int c0 = __ldg(&ecol[i]);
        int c1 = __ldg(&ecol[i + 1]);
        int c2 = __ldg(&ecol[i + 2]);
        int c3 = __ldg(&ecol[i + 3]);
        float v0 = __ldg(&eval[i]);
        float v1 = __ldg(&eval[i + 1]);
        float v2 = __ldg(&eval[i + 2]);
        float v3 = __ldg(&eval[i + 3]);
        acc = fmaf(v0, __ldg(&x[c0 * DD + lane]), acc);
        acc = fmaf(v1, __ldg(&x[c1 * DD + lane]), acc);
        acc = fmaf(v2, __ldg(&x[c2 * DD + lane]), acc);
        acc = fmaf(v3, __ldg(&x[c3 * DD + lane]), acc);
    }
    for (; i < e; i++)
        acc = fmaf(__ldg(&eval[i]), __ldg(&x[__ldg(&ecol[i]) * DD + lane]), acc);
    int idx = r * DD + lane;
    out[idx] = acc;
    accum[idx] += acc;
}

__global__ void k_spmm_dual(const int* __restrict__ rp, const int* __restrict__ ecol,
                            const float* __restrict__ eval,
                            const float* __restrict__ xTop, const float* __restrict__ xBot,
                            int split, float* __restrict__ accum, int nrows) {
    int r = blockIdx.x * 8 + (threadIdx.x >> 5);
    if (r >= nrows) return;
    int lane = threadIdx.x & 31;
    int s = __ldg(&rp[r]);
    int e = __ldg(&rp[r + 1]);
    float acc = 0.f;
    for (int i = s; i < e; i++) {
        int c = __ldg(&ecol[i]);
        float v = __ldg(&eval[i]);
        float xv = (c < split) ? __ldg(&xTop[c * DD + lane])
                               : __ldg(&xBot[(c - split) * DD + lane]);
        acc = fmaf(v, xv, acc);
    }
    accum[r * DD + lane] += acc;
}

// ----------------------------- dense GEMM (tf32 tensor cores) --------------
__device__ __forceinline__ uint32_t f2tf32(float f) {
    uint32_t r;
    asm("cvt.rna.tf32.f32 %0, %1;" : "=r"(r) : "f"(f));
    return r;
}

__device__ __forceinline__ void mma_tf32(float* d, const uint32_t* a, const uint32_t* b) {
    asm volatile(
        "mma.sync.aligned.m16n8k8.row.col.f32.tf32.tf32.f32 "
        "{%0,%1,%2,%3}, {%4,%5,%6,%7}, {%8,%9}, {%0,%1,%2,%3};"
        : "+f"(d[0]), "+f"(d[1]), "+f"(d[2]), "+f"(d[3])
        : "r"(a[0]), "r"(a[1]), "r"(a[2]), "r"(a[3]), "r"(b[0]), "r"(b[1]));
}

// y[N,32] = A[N,N] @ x[N,32], split-K into KSPLIT deterministic partials.
// CTA: 256 rows x 32 cols, K-tile 32. 8 warps, each warp covers 32 rows
// (2 m16 tiles sharing B fragments). KS must be a multiple of 32.
__global__ void __launch_bounds__(256) k_gemm_tc(const float* __restrict__ A,
                                                const float* __restrict__ x,
                                                float* __restrict__ part, int N, int KS) {
    __shared__ uint32_t As[256][36];  // pad 4: conflict-free frag gathers
    __shared__ uint32_t xs[32][40];   // pad 8: conflict-free frag gathers
    int tid = threadIdx.x;
    int warp = tid >> 5;
    int lane = tid & 31;
    int gid = lane >> 2;   // 0..7
    int tig = lane & 3;    // 0..3
    int row0 = blockIdx.x * 256;
    int kbeg = blockIdx.y * KS;
    int kend = min(kbeg + KS, N);

    float acc[2][4][4];
#pragma unroll
    for (int mt = 0; mt < 2; mt++)
#pragma unroll
        for (int nt = 0; nt < 4; nt++)
#pragma unroll
            for (int q = 0; q < 4; q++) acc[mt][nt][q] = 0.f;

    for (int k0 = kbeg; k0 < kend; k0 += 32) {
        // ---- load A tile: 256 rows x 32 k ----
#pragma unroll
        for (int j = 0; j < 8; j++) {
            int s = j * 256 + tid;
            int r = s >> 3;
            int kv = (s & 7) * 4;
            int gr = row0 + r;
            int gk = k0 + kv;
            uint32_t w0 = 0, w1 = 0, w2 = 0, w3 = 0;
            if (gr < N) {
                if (gk + 4 <= kend) {
                    float4 v = *reinterpret_cast<const float4*>(&A[(size_t)gr * N + gk]);
                    w0 = f2tf32(v.x); w1 = f2tf32(v.y); w2 = f2tf32(v.z); w3 = f2tf32(v.w);
                } else {
                    const float* p = &A[(size_t)gr * N];
                    if (gk + 0 < kend) w0 = f2tf32(p[gk + 0]);
                    if (gk + 1 < kend) w1 = f2tf32(p[gk + 1]);
                    if (gk + 2 < kend) w2 = f2tf32(p[gk + 2]);
                    if (gk + 3 < kend) w3 = f2tf32(p[gk + 3]);
                }
            }
            As[r][kv + 0] = w0; As[r][kv + 1] = w1;
            As[r][kv + 2] = w2; As[r][kv + 3] = w3;
        }
        // ---- load x tile: 32 k x 32 n ----
        {
            int r = tid >> 3;          // k row 0..31
            int nv = (tid & 7) * 4;    // col
            int gk = k0 + r;
            uint32_t w0 = 0, w1 = 0, w2 = 0, w3 = 0;
            if (gk < kend) {
                float4 v = *reinterpret_cast<const float4*>(&x[gk * 32 + nv]);
                w0 = f2tf32(v.x); w1 = f2tf32(v.y); w2 = f2tf32(v.z); w3 = f2tf32(v.w);
            }
            xs[r][nv + 0] = w0; xs[r][nv + 1] = w1;
            xs[r][nv + 2] = w2; xs[r][nv + 3] = w3;
        }
        __syncthreads();

        int wr = warp * 32;
#pragma unroll
        for (int kk = 0; kk < 4; kk++) {
            uint32_t b[4][2];
#pragma unroll
            for (int nt = 0; nt < 4; nt++) {
                b[nt][0] = xs[kk * 8 + tig][nt * 8 + gid];
                b[nt][1] = xs[kk * 8 + tig + 4][nt * 8 + gid];
            }
#pragma unroll
            for (int mt = 0; mt < 2; mt++) {
                uint32_t a[4];
                int rb = wr + mt * 16;
                a[0] = As[rb + gid][kk * 8 + tig];
                a[1] = As[rb + gid + 8][kk * 8 + tig];
                a[2] = As[rb + gid][kk * 8 + tig + 4];
                a[3] = As[rb + gid + 8][kk * 8 + tig + 4];
#pragma unroll
                for (int nt = 0; nt < 4; nt++) mma_tf32(acc[mt][nt], a, b[nt]);
            }
        }
        __syncthreads();
    }

    // ---- store partials ----
    int kseg = blockIdx.y;
#pragma unroll
    for (int mt = 0; mt < 2; mt++) {
#pragma unroll
        for (int nt = 0; nt < 4; nt++) {
            int rr = row0 + warp * 32 + mt * 16 + gid;
            int cc = nt * 8 + 2 * tig;
            if (rr < N)
                *reinterpret_cast<float2*>(&part[((size_t)kseg * N + rr) * 32 + cc]) =
                    make_float2(acc[mt][nt][0], acc[mt][nt][1]);
            int rr2 = rr + 8;
            if (rr2 < N)
                *reinterpret_cast<float2*>(&part[((size_t)kseg * N + rr2) * 32 + cc]) =
                    make_float2(acc[mt][nt][2], acc[mt][nt][3]);
        }
    }
}

// sum the KSPLIT partials; write y; update acc (init from xinit or accumulate)
__global__ void k_reduce(const float* __restrict__ part, float* __restrict__ y,
                         float* __restrict__ acc, const float* __restrict__ xinit,
                         int N, int initFlag) {
    int idx = blockIdx.x * blockDim.x + threadIdx.x;
    if (idx >= N * 32) return;
    float s = 0.f;
#pragma unroll
    for (int q = 0; q < KSPLIT; q++) s += part[(size_t)q * N * 32 + idx];
    y[idx] = s;
    if (initFlag) acc[idx] = xinit[idx] + s;
    else acc[idx] += s;
}

// ----------------------------- elementwise ---------------------------------
__global__ void k_initUI(const float* __restrict__ ue, const float* __restrict__ ie,
                         float* bufA, float* sum) {
    int i = blockIdx.x * blockDim.x + threadIdx.x;
    if (i >= UI_N * DD) return;
    float v = (i < U_N * DD) ? ue[i] : ie[i - U_N * DD];
    bufA[i] = v;
    sum[i] = v;
}

__global__ void k_initGI(const float* __restrict__ ge, const float* __restrict__ itemsrc,
                         float* giA, float* sum) {
    int i = blockIdx.x * blockDim.x + threadIdx.x;
    if (i >= GI_N * DD) return;
    float v = (i < G_N * DD) ? ge[i] : itemsrc[i - G_N * DD];
    giA[i] = v;
    sum[i] = v;
}

__global__ void k_scale(float* __restrict__ o, const float* __restrict__ in, float s, int n) {
    int i = blockIdx.x * blockDim.x + threadIdx.x;
    if (i < n) o[i] = in[i] * s;
}

__global__ void k_copy(float* __restrict__ o, const float* __restrict__ in, int n) {
    int i = blockIdx.x * blockDim.x + threadIdx.x;
    if (i < n) o[i] = in[i];
}

__global__ void k_add(float* __restrict__ o, const float* __restrict__ in, int n) {
    int i = blockIdx.x * blockDim.x + threadIdx.x;
    if (i < n) o[i] += in[i];
}

// ----------------------------- pooling / gate / predict --------------------
__global__ void k_pool(const int* __restrict__ users, const float* __restrict__ mask,
                       const float* __restrict__ accU, float* __restrict__ gul) {
    int g = blockIdx.x * 8 + (threadIdx.x >> 5);
    if (g >= G_N) return;
    int lane = threadIdx.x & 31;
    float a = 0.f;
#pragma unroll
    for (int l = 0; l < LM; l++) {
        int u = __ldg(&users[g * LM + l]);
        float m = __ldg(&mask[g * LM + l]);
        a = fmaf(m, __ldg(&accU[u * DD + lane]), a);
    }
    gul[g * DD + lane] = a;
}

__global__ void k_gate(const float* __restrict__ gpart, const float* __restrict__ gul,
                       const float* __restrict__ w1, const float* __restrict__ b1,
                       const float* __restrict__ w2, const float* __restrict__ b2,
                       float* __restrict__ gfinal) {
    int g = blockIdx.x * 8 + (threadIdx.x >> 5);
    if (g >= G_N) return;
    int lane = threadIdx.x & 31;
    float xg = gpart[g * DD + lane] * 0.25f;
    float xu = gul[g * DD + lane];
    float h1 = __ldg(&b1[lane]);
    float h2 = h1;
#pragma unroll
    for (int k = 0; k < 32; k++) {
        float w = __ldg(&w1[k * 32 + lane]);
        h1 = fmaf(__shfl_sync(FULL, xg, k), w, h1);
        h2 = fmaf(__shfl_sync(FULL, xu, k), w, h2);
    }
    h1 = fmaxf(h1, 0.f);
    h2 = fmaxf(h2, 0.f);
    float w2l = __ldg(&w2[lane]);
    float s1 = h1 * w2l;
    float s2 = h2 * w2l;
#pragma unroll
    for (int o = 16; o; o >>= 1) {
        s1 += __shfl_xor_sync(FULL, s1, o);
        s2 += __shfl_xor_sync(FULL, s2, o);
    }
    float bb = __ldg(&b2[0]);
    float wg = 1.f / (1.f + expf(-(s1 + bb)));
    float wu = 1.f / (1.f + expf(-(s2 + bb)));
    gfinal[g * DD + lane] = wg * xg + wu * xu;
}

__global__ void k_pred(const int* __restrict__ ginp, const int* __restrict__ iinp,
                       const float* __restrict__ gfinal, const float* __restrict__ accI,
                       const float* __restrict__ pw1, const float* __restrict__ pb1,
                       const float* __restrict__ pw2, const float* __restrict__ pb2,
                       float* __restrict__ out) {
    int b = blockIdx.x * 8 + (threadIdx.x >> 5);
    if (b >= B_N) return;
    int lane = threadIdx.x & 31;
    int g = __ldg(&ginp[b]);
    int it = __ldg(&iinp[b]);
    float t = gfinal[g * DD + lane] * accI[it * DD + lane];
    int j = lane & 7;
    float p = __ldg(&pb1[j]);
#pragma unroll
    for (int k = 0; k < 32; k++) {
        float a = __shfl_sync(FULL, t, k);
        p = fmaf(a, __ldg(&pw1[k * 8 + j]), p);
    }
    p = fmaxf(p, 0.f);
    float s = (lane < 8) ? p * __ldg(&pw2[j]) : 0.f;
#pragma unroll
    for (int o = 16; o; o >>= 1) s += __shfl_xor_sync(FULL, s, o);
    if (lane == 0) out[b] = 1.f / (1.f + expf(-(s + __ldg(&pb2[0]))));
}

// ----------------------------- launch --------------------------------------
extern "C" void kernel_launch(void* const* d_in, const int* in_sizes, int n_in,
                              void* d_out, int out_size) {
    (void)in_sizes; (void)n_in; (void)out_size;
    const int* ginp = (const int*)d_in[0];
    const int* iinp = (const int*)d_in[1];
    const float* user_emb = (const float*)d_in[2];
    const float* group_emb = (const float*)d_in[3];
    const float* item_emb = (const float*)d_in[4];
    const int* ui_rows = (const int*)d_in[5];
    const int* ui_cols = (const int*)d_in[6];
    const float* ui_vals = (const float*)d_in[7];
    const int* gi_rows = (const int*)d_in[8];
    const int* gi_cols = (const int*)d_in[9];
    const float* gi_vals = (const float*)d_in[10];
    const float* ovU = (const float*)d_in[11];
    const float* ovI = (const float*)d_in[12];
    const int* agu = (const int*)d_in[13];
    const float* agm = (const float*)d_in[14];
    const float* gw1 = (const float*)d_in[15];
    const float* gb1 = (const float*)d_in[16];
    const float* gw2 = (const float*)d_in[17];
    const float* gb2 = (const float*)d_in[18];
    const float* pw1 = (const float*)d_in[19];
    const float* pb1 = (const float*)d_in[20];
    const float* pw2 = (const float*)d_in[21];
    const float* pb2 = (const float*)d_in[22];
    float* out = (float*)d_out;

    float *bufA, *bufB, *bufC, *sumUI, *meanUI, *giA, *giB, *sumGI;
    float *gpart, *gul, *gfinal, *iemb, *t1, *t2, *accU, *it1, *it2, *accI;
    float *uiev, *giev, *part;
    int *uicnt, *uirp, *uicur, *uiecol, *gicnt, *girp, *gicur, *giecol;
    cudaGetSymbolAddress((void**)&bufA, g_bufA);
    cudaGetSymbolAddress((void**)&bufB, g_bufB);
    cudaGetSymbolAddress((void**)&bufC, g_bufC);
    cudaGetSymbolAddress((void**)&sumUI, g_sumUI);
    cudaGetSymbolAddress((void**)&meanUI, g_meanUI);
    cudaGetSymbolAddress((void**)&giA, g_giA);
    cudaGetSymbolAddress((void**)&giB, g_giB);
    cudaGetSymbolAddress((void**)&sumGI, g_sumGI);
    cudaGetSymbolAddress((void**)&gpart, g_gpart);
    cudaGetSymbolAddress((void**)&gul, g_gul);
    cudaGetSymbolAddress((void**)&gfinal, g_gfinal);
    cudaGetSymbolAddress((void**)&iemb, g_iemb);
    cudaGetSymbolAddress((void**)&t1, g_t1);
    cudaGetSymbolAddress((void**)&t2, g_t2);
    cudaGetSymbolAddress((void**)&accU, g_accU);
    cudaGetSymbolAddress((void**)&it1, g_it1);
    cudaGetSymbolAddress((void**)&it2, g_it2);
    cudaGetSymbolAddress((void**)&accI, g_accI);
    cudaGetSymbolAddress((void**)&uiev, g_uiev);
    cudaGetSymbolAddress((void**)&giev, g_giev);
    cudaGetSymbolAddress((void**)&part, g_part);
    cudaGetSymbolAddress((void**)&uicnt, g_uicnt);
    cudaGetSymbolAddress((void**)&uirp, g_uirp);
    cudaGetSymbolAddress((void**)&uicur, g_uicur);
    cudaGetSymbolAddress((void**)&uiecol, g_uiecol);
    cudaGetSymbolAddress((void**)&gicnt, g_gicnt);
    cudaGetSymbolAddress((void**)&girp, g_girp);
    cudaGetSymbolAddress((void**)&gicur, g_gicur);
    cudaGetSymbolAddress((void**)&giecol, g_giecol);

    // ---- CSR build for both graphs ----
    k_zero_i<<<(UI_N + 255) / 256, 256>>>(uicnt, UI_N);
    k_zero_i<<<(GI_N + 255) / 256, 256>>>(gicnt, GI_N);
    k_hist<<<(NNZ_UI + 255) / 256, 256>>>(ui_rows, uicnt, NNZ_UI);
    k_hist<<<(NNZ_GI + 255) / 256, 256>>>(gi_rows, gicnt, NNZ_GI);
    k_scan<<<1, 1024>>>(uicnt, uirp, uicur, UI_N);
    k_scan<<<1, 1024>>>(gicnt, girp, gicur, GI_N);
    k_scatter<<<(NNZ_UI + 255) / 256, 256>>>(ui_rows, ui_cols, ui_vals, uicur, uiecol, uiev, NNZ_UI);
    k_scatter<<<(NNZ_GI + 255) / 256, 256>>>(gi_rows, gi_cols, gi_vals, gicur, giecol, giev, NNZ_GI);

    // ---- user-item propagation (3 layers) ----
    k_initUI<<<(UI_N * DD + 255) / 256, 256>>>(user_emb, item_emb, bufA, sumUI);
    k_spmm<<<(UI_N + 7) / 8, 256>>>(uirp, uiecol, uiev, bufA, bufB, sumUI, UI_N);
    k_spmm<<<(UI_N + 7) / 8, 256>>>(uirp, uiecol, uiev, bufB, bufC, sumUI, UI_N);
    k_spmm<<<(UI_N + 7) / 8, 256>>>(uirp, uiecol, uiev, bufC, bufA, sumUI, UI_N);
    k_scale<<<(UI_N * DD + 255) / 256, 256>>>(meanUI, sumUI, 0.25f, UI_N * DD);

    // ---- group-item propagation ----
    k_initGI<<<(GI_N * DD + 255) / 256, 256>>>(group_emb, meanUI + U_N * DD, giA, sumGI);
    k_copy<<<(G_N * DD + 255) / 256, 256>>>(gpart, group_emb, G_N * DD);
    k_spmm<<<(GI_N + 7) / 8, 256>>>(girp, giecol, giev, giA, giB, sumGI, GI_N);
    k_spmm<<<(GI_N + 7) / 8, 256>>>(girp, giecol, giev, giB, giA, sumGI, GI_N);
    k_add<<<(G_N * DD + 255) / 256, 256>>>(gpart, giA, G_N * DD);
    k_spmm<<<(GI_N + 7) / 8, 256>>>(girp, giecol, giev, giA, giB, sumGI, GI_N);
    k_scale<<<(I_N * DD + 255) / 256, 256>>>(iemb, sumGI + G_N * DD, 0.25f, I_N * DD);
    k_spmm_dual<<<(G_N + 7) / 8, 256>>>(girp, giecol, giev, group_emb, item_emb, G_N, gpart, G_N);
    k_spmm_dual<<<(G_N + 7) / 8, 256>>>(girp, giecol, giev, group_emb, bufC + U_N * DD, G_N, gpart, G_N);

    // ---- user social power-series (2 dense GEMM layers, tf32 TC) ----
    {
        int KS = ((U_N + KSPLIT - 1) / KSPLIT + 31) & ~31;  // 640, mult of 32
        dim3 grid((U_N + 255) / 256, KSPLIT);
        k_gemm_tc<<<grid, 256>>>(ovU, meanUI, part, U_N, KS);
        k_reduce<<<(U_N * DD + 255) / 256, 256>>>(part, t1, accU, meanUI, U_N, 1);
        k_gemm_tc<<<grid, 256>>>(ovU, t1, part, U_N, KS);
        k_reduce<<<(U_N * DD + 255) / 256, 256>>>(part, t2, accU, meanUI, U_N, 0);
    }
    k_pool<<<(G_N + 7) / 8, 256>>>(agu, agm, accU, gul);
    k_gate<<<(G_N + 7) / 8, 256>>>(gpart, gul, gw1, gb1, gw2, gb2, gfinal);

    // ---- item social power-series ----
    {
        int KS = ((I_N + KSPLIT - 1) / KSPLIT + 31) & ~31;  // 512
        dim3 grid((I_N + 255) / 256, KSPLIT);
        k_gemm_tc<<<grid, 256>>>(ovI, iemb, part, I_N, KS);
        k_reduce<<<(I_N * DD + 255) / 256, 256>>>(part, it1, accI, iemb, I_N, 1);
        k_gemm_tc<<<grid, 256>>>(ovI, it1, part, I_N, KS);
        k_reduce<<<(I_N * DD + 255) / 256, 256>>>(part, it2, accI, iemb, I_N, 0);
    }

    // ---- predict ----
    k_pred<<<(B_N + 7) / 8, 256>>>(ginp, iinp, gfinal, accI, pw1, pb1, pw2, pb2, out);
}

// round 6
// speedup vs baseline: 1.0882x; 1.0382x over previous
#include <cuda_runtime.h>
#include <cstdint>
#include <math.h>

#define U_N 10000
#define G_N 3000
#define I_N 8000
#define DD 32
#define UI_N (U_N + I_N)   /* 18000 */
#define GI_N (G_N + I_N)   /* 11000 */
#define NNZ_UI 720000
#define NNZ_GI 440000
#define LM 20
#define B_N 4096
#define KSPLIT 16
#define FULL 0xffffffffu

// ----------------------------- static scratch -----------------------------
__device__ float g_bufB[UI_N * DD];
__device__ float g_bufC[UI_N * DD];
__device__ float g_sumUI[UI_N * DD];
__device__ float g_meanUI[UI_N * DD];
__device__ float g_giA[GI_N * DD];
__device__ float g_giB[GI_N * DD];
__device__ float g_sumGI[GI_N * DD];
__device__ float g_gpart[G_N * DD];
__device__ float g_gfinal[G_N * DD];
__device__ float g_iemb[I_N * DD];
__device__ float g_t1[U_N * DD];
__device__ float g_t2[U_N * DD];
__device__ float g_accU[U_N * DD];
__device__ float g_it1[I_N * DD];
__device__ float g_it2[I_N * DD];
__device__ float g_accI[I_N * DD];
__device__ float g_uiev[NNZ_UI];
__device__ float g_giev[NNZ_GI];
__device__ float g_part[KSPLIT * U_N * DD];

__device__ int g_uicnt[UI_N];
__device__ int g_uirp[UI_N + 1];
__device__ int g_uicur[UI_N];
__device__ int g_uiecol[NNZ_UI];
__device__ int g_gicnt[GI_N];
__device__ int g_girp[GI_N + 1];
__device__ int g_gicur[GI_N];
__device__ int g_giecol[NNZ_GI];

// ----------------------------- CSR build (fused both graphs) ---------------
__global__ void k_zero2(int* a, int* b) {
    int i = blockIdx.x * blockDim.x + threadIdx.x;
    if (i < UI_N) a[i] = 0;
    else if (i < UI_N + GI_N) b[i - UI_N] = 0;
}

__global__ void k_hist2(const int* __restrict__ r1, const int* __restrict__ r2,
                        int* c1, int* c2) {
    int i = blockIdx.x * blockDim.x + threadIdx.x;
    if (i < NNZ_UI) atomicAdd(&c1[r1[i]], 1);
    else if (i < NNZ_UI + NNZ_GI) atomicAdd(&c2[r2[i - NNZ_UI]], 1);
}

// grid=2 blocks, 1024 threads: block 0 scans UI, block 1 scans GI
__global__ void k_scan2(const int* __restrict__ cntA, int* rpA, int* curA,
                        const int* __restrict__ cntB, int* rpB, int* curB) {
    const int* cnt = blockIdx.x ? cntB : cntA;
    int* rp = blockIdx.x ? rpB : rpA;
    int* cur = blockIdx.x ? curB : curA;
    int n = blockIdx.x ? GI_N : UI_N;
    __shared__ int part[1024];
    int tid = threadIdx.x;
    int chunk = (n + 1023) >> 10;
    int s0 = tid * chunk;
    int s1 = min(s0 + chunk, n);
    int s = 0;
    for (int i = s0; i < s1; i++) s += cnt[i];
    part[tid] = s;
    __syncthreads();
    for (int off = 1; off < 1024; off <<= 1) {
        int v = (tid >= off) ? part[tid - off] : 0;
        __syncthreads();
        part[tid] += v;
        __syncthreads();
    }
    int base = (tid == 0) ? 0 : part[tid - 1];
    for (int i = s0; i < s1; i++) {
        rp[i] = base;
        cur[i] = base;
        base += cnt[i];
    }
    if (tid == 1023) rp[n] = part[1023];
}

__global__ void k_scatter2(const int* __restrict__ r1, const int* __restrict__ c1,
                           const float* __restrict__ v1, int* cur1, int* ec1, float* ev1,
                           const int* __restrict__ r2, const int* __restrict__ c2,
                           const float* __restrict__ v2, int* cur2, int* ec2, float* ev2) {
    int i = blockIdx.x * blockDim.x + threadIdx.x;
    if (i < NNZ_UI) {
        int p = atomicAdd(&cur1[r1[i]], 1);
        ec1[p] = c1[i];
        ev1[p] = v1[i];
    } else if (i < NNZ_UI + NNZ_GI) {
        int j = i - NNZ_UI;
        int p = atomicAdd(&cur2[r2[j]], 1);
        ec2[p] = c2[j];
        ev2[p] = v2[j];
    }
}

// ----------------------------- SpMM variants --------------------------------
// Layer 1 on UI graph with virtual concat input + sum init (fuses initUI).
__global__ void k_spmm1(const int* __restrict__ rp, const int* __restrict__ ecol,
                        const float* __restrict__ eval,
                        const float* __restrict__ ue, const float* __restrict__ ie,
                        float* __restrict__ out, float* __restrict__ sum) {
    int r = blockIdx.x * 8 + (threadIdx.x >> 5);
    if (r >= UI_N) return;
    int lane = threadIdx.x & 31;
    int s = __ldg(&rp[r]);
    int e = __ldg(&rp[r + 1]);
    float acc = 0.f;
    for (int i = s; i < e; i++) {
        int c = __ldg(&ecol[i]);
        float v = __ldg(&eval[i]);
        float xv = (c < U_N) ? __ldg(&ue[c * DD + lane])
                             : __ldg(&ie[(c - U_N) * DD + lane]);
        acc = fmaf(v, xv, acc);
    }
    float own = (r < U_N) ? __ldg(&ue[r * DD + lane]) : __ldg(&ie[(r - U_N) * DD + lane]);
    int idx = r * DD + lane;
    out[idx] = acc;
    sum[idx] = own + acc;
}

// generic: out + accum
__global__ void k_spmm_mid(const int* __restrict__ rp, const int* __restrict__ ecol,
                           const float* __restrict__ eval, const float* __restrict__ x,
                           float* __restrict__ out, float* __restrict__ accum, int nrows) {
    int r = blockIdx.x * 8 + (threadIdx.x >> 5);
    if (r >= nrows) return;
    int lane = threadIdx.x & 31;
    int s = __ldg(&rp[r]);
    int e = __ldg(&rp[r + 1]);
    float acc = 0.f;
    int i = s;
    for (; i + 4 <= e; i += 4) {
        int c0 = __ldg(&ecol[i]);
        int c1 = __ldg(&ecol[i + 1]);
        int c2 = __ldg(&ecol[i + 2]);
        int c3 = __ldg(&ecol[i + 3]);
        float v0 = __ldg(&eval[i]);
        float v1 = __ldg(&eval[i + 1]);
        float v2 = __ldg(&eval[i + 2]);
        float v3 = __ldg(&eval[i + 3]);
        acc = fmaf(v0, __ldg(&x[c0 * DD + lane]), acc);
        acc = fmaf(v1, __ldg(&x[c1 * DD + lane]), acc);
        acc = fmaf(v2, __ldg(&x[c2 * DD + lane]), acc);
        acc = fmaf(v3, __ldg(&x[c3 * DD + lane]), acc);
    }
    for (; i < e; i++)
        acc = fmaf(__ldg(&eval[i]), __ldg(&x[__ldg(&ecol[i]) * DD + lane]), acc);
    int idx = r * DD + lane;
    out[idx] = acc;
    accum[idx] += acc;
}

// accumulate only (ui layer 3: out never consumed)
__global__ void k_spmm_acc(const int* __restrict__ rp, const int* __restrict__ ecol,
                           const float* __restrict__ eval, const float* __restrict__ x,
                           float* __restrict__ accum, int nrows) {
    int r = blockIdx.x * 8 + (threadIdx.x >> 5);
    if (r >= nrows) return;
    int lane = threadIdx.x & 31;
    int s = __ldg(&rp[r]);
    int e = __ldg(&rp[r + 1]);
    float acc = 0.f;
    int i = s;
    for (; i + 4 <= e; i += 4) {
        int c0 = __ldg(&ecol[i]);
        int c1 = __ldg(&ecol[i + 1]);
        int c2 = __ldg(&ecol[i + 2]);
        int c3 = __ldg(&ecol[i + 3]);
        float v0 = __ldg(&eval[i]);
        float v1 = __ldg(&eval[i + 1]);
        float v2 = __ldg(&eval[i + 2]);
        float v3 = __ldg(&eval[i + 3]);
        acc = fmaf(v0, __ldg(&x[c0 * DD + lane]), acc);
        acc = fmaf(v1, __ldg(&x[c1 * DD + lane]), acc);
        acc = fmaf(v2, __ldg(&x[c2 * DD + lane]), acc);
        acc = fmaf(v3, __ldg(&x[c3 * DD + lane]), acc);
    }
    for (; i < e; i++)
        acc = fmaf(__ldg(&eval[i]), __ldg(&x[__ldg(&ecol[i]) * DD + lane]), acc);
    accum[r * DD + lane] += acc;
}

// gi layer 2: out + accum, plus gpart += acc for group rows (fuses k_add)
__global__ void k_spmm_gi2(const int* __restrict__ rp, const int* __restrict__ ecol,
                           const float* __restrict__ eval, const float* __restrict__ x,
                           float* __restrict__ out, float* __restrict__ accum,
                           float* __restrict__ gpart) {
    int r = blockIdx.x * 8 + (threadIdx.x >> 5);
    if (r >= GI_N) return;
    int lane = threadIdx.x & 31;
    int s = __ldg(&rp[r]);
    int e = __ldg(&rp[r + 1]);
    float acc = 0.f;
    for (int i = s; i < e; i++)
        acc = fmaf(__ldg(&eval[i]), __ldg(&x[__ldg(&ecol[i]) * DD + lane]), acc);
    int idx = r * DD + lane;
    out[idx] = acc;
    accum[idx] += acc;
    if (r < G_N) gpart[idx] += acc;
}

// gi layer 3: item rows only; iemb = (sumGI + acc)/4 (fuses final scale)
__global__ void k_spmm_gi3(const int* __restrict__ rp, const int* __restrict__ ecol,
                           const float* __restrict__ eval, const float* __restrict__ x,
                           const float* __restrict__ sumGI, float* __restrict__ iemb) {
    int rl = blockIdx.x * 8 + (threadIdx.x >> 5);
    if (rl >= I_N) return;
    int r = G_N + rl;
    int lane = threadIdx.x & 31;
    int s = __ldg(&rp[r]);
    int e = __ldg(&rp[r + 1]);
    float acc = 0.f;
    for (int i = s; i < e; i++)
        acc = fmaf(__ldg(&eval[i]), __ldg(&x[__ldg(&ecol[i]) * DD + lane]), acc);
    iemb[rl * DD + lane] = (sumGI[r * DD + lane] + acc) * 0.25f;
}

// both odd g-layers in one pass: shared edge list, shared group-side gather
__global__ void k_spmm_dual2(const int* __restrict__ rp, const int* __restrict__ ecol,
                             const float* __restrict__ eval,
                             const float* __restrict__ ge,
                             const float* __restrict__ xb1, const float* __restrict__ xb2,
                             float* __restrict__ gpart) {
    int r = blockIdx.x * 8 + (threadIdx.x >> 5);
    if (r >= G_N) return;
    int lane = threadIdx.x & 31;
    int s = __ldg(&rp[r]);
    int e = __ldg(&rp[r + 1]);
    float a1 = 0.f, a2 = 0.f;
    for (int i = s; i < e; i++) {
        int c = __ldg(&ecol[i]);
        float v = __ldg(&eval[i]);
        if (c < G_N) {
            float xv = __ldg(&ge[c * DD + lane]);
            a1 = fmaf(v, xv, a1);
            a2 = fmaf(v, xv, a2);
        } else {
            int ci = (c - G_N) * DD + lane;
            a1 = fmaf(v, __ldg(&xb1[ci]), a1);
            a2 = fmaf(v, __ldg(&xb2[ci]), a2);
        }
    }
    gpart[r * DD + lane] += a1 + a2;
}

// meanUI = sumUI/4 ; giA/sumGI init ; gpart = group_emb  (one kernel)
__global__ void k_fusemid(const float* __restrict__ sumUI, float* __restrict__ meanUI,
                          const float* __restrict__ ge, float* __restrict__ giA,
                          float* __restrict__ sumGI, float* __restrict__ gpart) {
    int i = blockIdx.x * blockDim.x + threadIdx.x;
    const int T1 = UI_N * DD;
    const int T2 = T1 + GI_N * DD;
    const int T3 = T2 + G_N * DD;
    if (i < T1) {
        meanUI[i] = sumUI[i] * 0.25f;
    } else if (i < T2) {
        int j = i - T1;
        float v = (j < G_N * DD) ? ge[j] : sumUI[U_N * DD + (j - G_N * DD)] * 0.25f;
        giA[j] = v;
        sumGI[j] = v;
    } else if (i < T3) {
        int j = i - T2;
        gpart[j] = ge[j];
    }
}

// ----------------------------- dense GEMM (tf32 tensor cores) --------------
__device__ __forceinline__ uint32_t f2tf32(float f) {
    uint32_t r;
    asm("cvt.rna.tf32.f32 %0, %1;" : "=r"(r) : "f"(f));
    return r;
}

__device__ __forceinline__ void mma_tf32(float* d, const uint32_t* a, const uint32_t* b) {
    asm volatile(
        "mma.sync.aligned.m16n8k8.row.col.f32.tf32.tf32.f32 "
        "{%0,%1,%2,%3}, {%4,%5,%6,%7}, {%8,%9}, {%0,%1,%2,%3};"
        : "+f"(d[0]), "+f"(d[1]), "+f"(d[2]), "+f"(d[3])
        : "r"(a[0]), "r"(a[1]), "r"(a[2]), "r"(a[3]), "r"(b[0]), "r"(b[1]));
}

__global__ void __launch_bounds__(256) k_gemm_tc(const float* __restrict__ A,
                                                const float* __restrict__ x,
                                                float* __restrict__ part, int N, int KS) {
    __shared__ uint32_t As[256][36];
    __shared__ uint32_t xs[32][40];
    int tid = threadIdx.x;
    int warp = tid >> 5;
    int lane = tid & 31;
    int gid = lane >> 2;
    int tig = lane & 3;
    int row0 = blockIdx.x * 256;
    int kbeg = blockIdx.y * KS;
    int kend = min(kbeg + KS, N);

    float acc[2][4][4];
#pragma unroll
    for (int mt = 0; mt < 2; mt++)
#pragma unroll
        for (int nt = 0; nt < 4; nt++)
#pragma unroll
            for (int q = 0; q < 4; q++) acc[mt][nt][q] = 0.f;

    for (int k0 = kbeg; k0 < kend; k0 += 32) {
#pragma unroll
        for (int j = 0; j < 8; j++) {
            int s = j * 256 + tid;
            int r = s >> 3, kv = (s & 7) * 4;
            int gr = row0 + r, gk = k0 + kv;
            uint32_t w0 = 0, w1 = 0, w2 = 0, w3 = 0;
            if (gr < N) {
                if (gk + 4 <= kend) {
                    float4 v = *reinterpret_cast<const float4*>(&A[(size_t)gr * N + gk]);
                    w0 = f2tf32(v.x); w1 = f2tf32(v.y); w2 = f2tf32(v.z); w3 = f2tf32(v.w);
                } else {
                    const float* p = &A[(size_t)gr * N];
                    if (gk + 0 < kend) w0 = f2tf32(p[gk + 0]);
                    if (gk + 1 < kend) w1 = f2tf32(p[gk + 1]);
                    if (gk + 2 < kend) w2 = f2tf32(p[gk + 2]);
                    if (gk + 3 < kend) w3 = f2tf32(p[gk + 3]);
                }
            }
            As[r][kv + 0] = w0; As[r][kv + 1] = w1;
            As[r][kv + 2] = w2; As[r][kv + 3] = w3;
        }
        {
            int r = tid >> 3;
            int nv = (tid & 7) * 4;
            int gk = k0 + r;
            uint32_t w0 = 0, w1 = 0, w2 = 0, w3 = 0;
            if (gk < kend) {
                float4 v = *reinterpret_cast<const float4*>(&x[gk * 32 + nv]);
                w0 = f2tf32(v.x); w1 = f2tf32(v.y); w2 = f2tf32(v.z); w3 = f2tf32(v.w);
            }
            xs[r][nv + 0] = w0; xs[r][nv + 1] = w1;
            xs[r][nv + 2] = w2; xs[r][nv + 3] = w3;
        }
        __syncthreads();

        int wr = warp * 32;
#pragma unroll
        for (int kk = 0; kk < 4; kk++) {
            uint32_t b[4][2];
#pragma unroll
            for (int nt = 0; nt < 4; nt++) {
                b[nt][0] = xs[kk * 8 + tig][nt * 8 + gid];
                b[nt][1] = xs[kk * 8 + tig + 4][nt * 8 + gid];
            }
#pragma unroll
            for (int mt = 0; mt < 2; mt++) {
                uint32_t a[4];
                int rb = wr + mt * 16;
                a[0] = As[rb + gid][kk * 8 + tig];
                a[1] = As[rb + gid + 8][kk * 8 + tig];
                a[2] = As[rb + gid][kk * 8 + tig + 4];
                a[3] = As[rb + gid + 8][kk * 8 + tig + 4];
#pragma unroll
                for (int nt = 0; nt < 4; nt++) mma_tf32(acc[mt][nt], a, b[nt]);
            }
        }
        __syncthreads();
    }

    int kseg = blockIdx.y;
#pragma unroll
    for (int mt = 0; mt < 2; mt++) {
#pragma unroll
        for (int nt = 0; nt < 4; nt++) {
            int rr = row0 + warp * 32 + mt * 16 + gid;
            int cc = nt * 8 + 2 * tig;
            if (rr < N)
                *reinterpret_cast<float2*>(&part[((size_t)kseg * N + rr) * 32 + cc]) =
                    make_float2(acc[mt][nt][0], acc[mt][nt][1]);
            int rr2 = rr + 8;
            if (rr2 < N)
                *reinterpret_cast<float2*>(&part[((size_t)kseg * N + rr2) * 32 + cc]) =
                    make_float2(acc[mt][nt][2], acc[mt][nt][3]);
        }
    }
}

__global__ void k_reduce(const float* __restrict__ part, float* __restrict__ y,
                         float* __restrict__ acc, const float* __restrict__ xinit,
                         int N, int initFlag) {
    int idx = blockIdx.x * blockDim.x + threadIdx.x;
    if (idx >= N * 32) return;
    float s = 0.f;
#pragma unroll
    for (int q = 0; q < KSPLIT; q++) s += part[(size_t)q * N * 32 + idx];
    y[idx] = s;
    if (initFlag) acc[idx] = xinit[idx] + s;
    else acc[idx] += s;
}

// ----------------------------- pool+gate fused / predict -------------------
__global__ void k_poolgate(const int* __restrict__ users, const float* __restrict__ mask,
                           const float* __restrict__ accU, const float* __restrict__ gpart,
                           const float* __restrict__ w1, const float* __restrict__ b1,
                           const float* __restrict__ w2, const float* __restrict__ b2,
                           float* __restrict__ gfinal) {
    int g = blockIdx.x * 8 + (threadIdx.x >> 5);
    if (g >= G_N) return;
    int lane = threadIdx.x & 31;
    float xu = 0.f;
#pragma unroll
    for (int l = 0; l < LM; l++) {
        int u = __ldg(&users[g * LM + l]);
        float m = __ldg(&mask[g * LM + l]);
        xu = fmaf(m, __ldg(&accU[u * DD + lane]), xu);
    }
    float xg = gpart[g * DD + lane] * 0.25f;
    float h1 = __ldg(&b1[lane]);
    float h2 = h1;
#pragma unroll
    for (int k = 0; k < 32; k++) {
        float w = __ldg(&w1[k * 32 + lane]);
        h1 = fmaf(__shfl_sync(FULL, xg, k), w, h1);
        h2 = fmaf(__shfl_sync(FULL, xu, k), w, h2);
    }
    h1 = fmaxf(h1, 0.f);
    h2 = fmaxf(h2, 0.f);
    float w2l = __ldg(&w2[lane]);
    float s1 = h1 * w2l;
    float s2 = h2 * w2l;
#pragma unroll
    for (int o = 16; o; o >>= 1) {
        s1 += __shfl_xor_sync(FULL, s1, o);
        s2 += __shfl_xor_sync(FULL, s2, o);
    }
    float bb = __ldg(&b2[0]);
    float wg = 1.f / (1.f + expf(-(s1 + bb)));
    float wu = 1.f / (1.f + expf(-(s2 + bb)));
    gfinal[g * DD + lane] = wg * xg + wu * xu;
}

__global__ void k_pred(const int* __restrict__ ginp, const int* __restrict__ iinp,
                       const float* __restrict__ gfinal, const float* __restrict__ accI,
                       const float* __restrict__ pw1, const float* __restrict__ pb1,
                       const float* __restrict__ pw2, const float* __restrict__ pb2,
                       float* __restrict__ out) {
    int b = blockIdx.x * 8 + (threadIdx.x >> 5);
    if (b >= B_N) return;
    int lane = threadIdx.x & 31;
    int g = __ldg(&ginp[b]);
    int it = __ldg(&iinp[b]);
    float t = gfinal[g * DD + lane] * accI[it * DD + lane];
    int j = lane & 7;
    float p = __ldg(&pb1[j]);
#pragma unroll
    for (int k = 0; k < 32; k++) {
        float a = __shfl_sync(FULL, t, k);
        p = fmaf(a, __ldg(&pw1[k * 8 + j]), p);
    }
    p = fmaxf(p, 0.f);
    float s = (lane < 8) ? p * __ldg(&pw2[j]) : 0.f;
#pragma unroll
    for (int o = 16; o; o >>= 1) s += __shfl_xor_sync(FULL, s, o);
    if (lane == 0) out[b] = 1.f / (1.f + expf(-(s + __ldg(&pb2[0]))));
}

// ----------------------------- launch --------------------------------------
extern "C" void kernel_launch(void* const* d_in, const int* in_sizes, int n_in,
                              void* d_out, int out_size) {
    (void)in_sizes; (void)n_in; (void)out_size;
    const int* ginp = (const int*)d_in[0];
    const int* iinp = (const int*)d_in[1];
    const float* user_emb = (const float*)d_in[2];
    const float* group_emb = (const float*)d_in[3];
    const float* item_emb = (const float*)d_in[4];
    const int* ui_rows = (const int*)d_in[5];
    const int* ui_cols = (const int*)d_in[6];
    const float* ui_vals = (const float*)d_in[7];
    const int* gi_rows = (const int*)d_in[8];
    const int* gi_cols = (const int*)d_in[9];
    const float* gi_vals = (const float*)d_in[10];
    const float* ovU = (const float*)d_in[11];
    const float* ovI = (const float*)d_in[12];
    const int* agu = (const int*)d_in[13];
    const float* agm = (const float*)d_in[14];
    const float* gw1 = (const float*)d_in[15];
    const float* gb1 = (const float*)d_in[16];
    const float* gw2 = (const float*)d_in[17];
    const float* gb2 = (const float*)d_in[18];
    const float* pw1 = (const float*)d_in[19];
    const float* pb1 = (const float*)d_in[20];
    const float* pw2 = (const float*)d_in[21];
    const float* pb2 = (const float*)d_in[22];
    float* out = (float*)d_out;

    float *bufB, *bufC, *sumUI, *meanUI, *giA, *giB, *sumGI;
    float *gpart, *gfinal, *iemb, *t1, *t2, *accU, *it1, *it2, *accI;
    float *uiev, *giev, *part;
    int *uicnt, *uirp, *uicur, *uiecol, *gicnt, *girp, *gicur, *giecol;
    cudaGetSymbolAddress((void**)&bufB, g_bufB);
    cudaGetSymbolAddress((void**)&bufC, g_bufC);
    cudaGetSymbolAddress((void**)&sumUI, g_sumUI);
    cudaGetSymbolAddress((void**)&meanUI, g_meanUI);
    cudaGetSymbolAddress((void**)&giA, g_giA);
    cudaGetSymbolAddress((void**)&giB, g_giB);
    cudaGetSymbolAddress((void**)&sumGI, g_sumGI);
    cudaGetSymbolAddress((void**)&gpart, g_gpart);
    cudaGetSymbolAddress((void**)&gfinal, g_gfinal);
    cudaGetSymbolAddress((void**)&iemb, g_iemb);
    cudaGetSymbolAddress((void**)&t1, g_t1);
    cudaGetSymbolAddress((void**)&t2, g_t2);
    cudaGetSymbolAddress((void**)&accU, g_accU);
    cudaGetSymbolAddress((void**)&it1, g_it1);
    cudaGetSymbolAddress((void**)&it2, g_it2);
    cudaGetSymbolAddress((void**)&accI, g_accI);
    cudaGetSymbolAddress((void**)&uiev, g_uiev);
    cudaGetSymbolAddress((void**)&giev, g_giev);
    cudaGetSymbolAddress((void**)&part, g_part);
    cudaGetSymbolAddress((void**)&uicnt, g_uicnt);
    cudaGetSymbolAddress((void**)&uirp, g_uirp);
    cudaGetSymbolAddress((void**)&uicur, g_uicur);
    cudaGetSymbolAddress((void**)&uiecol, g_uiecol);
    cudaGetSymbolAddress((void**)&gicnt, g_gicnt);
    cudaGetSymbolAddress((void**)&girp, g_girp);
    cudaGetSymbolAddress((void**)&gicur, g_gicur);
    cudaGetSymbolAddress((void**)&giecol, g_giecol);

    // ---- CSR build (4 launches, both graphs fused) ----
    k_zero2<<<(UI_N + GI_N + 255) / 256, 256>>>(uicnt, gicnt);
    k_hist2<<<(NNZ_UI + NNZ_GI + 255) / 256, 256>>>(ui_rows, gi_rows, uicnt, gicnt);
    k_scan2<<<2, 1024>>>(uicnt, uirp, uicur, gicnt, girp, gicur);
    k_scatter2<<<(NNZ_UI + NNZ_GI + 255) / 256, 256>>>(
        ui_rows, ui_cols, ui_vals, uicur, uiecol, uiev,
        gi_rows, gi_cols, gi_vals, gicur, giecol, giev);

    // ---- user-item propagation (3 layers) ----
    k_spmm1<<<(UI_N + 7) / 8, 256>>>(uirp, uiecol, uiev, user_emb, item_emb, bufB, sumUI);
    k_spmm_mid<<<(UI_N + 7) / 8, 256>>>(uirp, uiecol, uiev, bufB, bufC, sumUI, UI_N);
    k_spmm_acc<<<(UI_N + 7) / 8, 256>>>(uirp, uiecol, uiev, bufC, sumUI, UI_N);

    // ---- meanUI + GI init + gpart init (1 launch) ----
    {
        int tot = UI_N * DD + GI_N * DD + G_N * DD;
        k_fusemid<<<(tot + 255) / 256, 256>>>(sumUI, meanUI, group_emb, giA, sumGI, gpart);
    }

    // ---- group-item propagation ----
    k_spmm_mid<<<(GI_N + 7) / 8, 256>>>(girp, giecol, giev, giA, giB, sumGI, GI_N);
    k_spmm_gi2<<<(GI_N + 7) / 8, 256>>>(girp, giecol, giev, giB, giA, sumGI, gpart);
    k_spmm_gi3<<<(I_N + 7) / 8, 256>>>(girp, giecol, giev, giA, sumGI, iemb);
    k_spmm_dual2<<<(G_N + 7) / 8, 256>>>(girp, giecol, giev, group_emb, item_emb,
                                         bufC + U_N * DD, gpart);

    // ---- user social power-series (tf32 TC) ----
    {
        int KS = ((U_N + KSPLIT - 1) / KSPLIT + 31) & ~31;  // 640
        dim3 grid((U_N + 255) / 256, KSPLIT);
        k_gemm_tc<<<grid, 256>>>(ovU, meanUI, part, U_N, KS);
        k_reduce<<<(U_N * DD + 255) / 256, 256>>>(part, t1, accU, meanUI, U_N, 1);
        k_gemm_tc<<<grid, 256>>>(ovU, t1, part, U_N, KS);
        k_reduce<<<(U_N * DD + 255) / 256, 256>>>(part, t2, accU, meanUI, U_N, 0);
    }

    // ---- item social power-series ----
    {
        int KS = ((I_N + KSPLIT - 1) / KSPLIT + 31) & ~31;  // 512
        dim3 grid((I_N + 255) / 256, KSPLIT);
        k_gemm_tc<<<grid, 256>>>(ovI, iemb, part, I_N, KS);
        k_reduce<<<(I_N * DD + 255) / 256, 256>>>(part, it1, accI, iemb, I_N, 1);
        k_gemm_tc<<<grid, 256>>>(ovI, it1, part, I_N, KS);
        k_reduce<<<(I_N * DD + 255) / 256, 256>>>(part, it2, accI, iemb, I_N, 0);
    }

    // ---- pool+gate fused, then predict ----
    k_poolgate<<<(G_N + 7) / 8, 256>>>(agu, agm, accU, gpart, gw1, gb1, gw2, gb2, gfinal);
    k_pred<<<(B_N + 7) / 8, 256>>>(ginp, iinp, gfinal, accI, pw1, pb1, pw2, pb2, out);
}